// round 8
// baseline (speedup 1.0000x reference)
#include <cuda_runtime.h>
#include <cuda_bf16.h>

typedef unsigned int       u32;
typedef unsigned long long u64;

#define NSEQ 2048
#define TT   4096
#define V3T  60
#define NT   9

// byte strides (odd multiples of 16 -> conflict-free ldmatrix)
#define SA1 112
#define SA2 144
#define SA3 272

// arena byte offsets
#define OA1 0u
#define OA2 57792u                 // 516*112
#define OA3 95232u                 // +260*144
#define OB1 131136u                // +132*272
#define OB2 136512u                // +3*16*112
#define OB3 150336u                // +3*32*144
#define ABSZ 163392u               // +3*16*272
#define B1TAP 1792u                // 16*112
#define B2TAP 4608u                // 32*144
#define B3TAP 4352u                // 16*272

#define SMEM_BYTES (4096 + ABSZ)

__device__ float g_feat[NSEQ * 16];

// ---------- helpers ----------
__device__ __forceinline__ u32 smem_u32p(const void* p) {
    u32 a;
    asm("{ .reg .u64 t; cvta.to.shared.u64 t, %1; cvt.u32.u64 %0, t; }" : "=r"(a) : "l"(p));
    return a;
}
__device__ __forceinline__ void sts32(u32 a, u32 v) {
    asm volatile("st.shared.b32 [%0], %1;" :: "r"(a), "r"(v) : "memory");
}
__device__ __forceinline__ void sts64v(u32 a, u32 lo, u32 hi) {
    asm volatile("st.shared.v2.b32 [%0], {%1, %2};" :: "r"(a), "r"(lo), "r"(hi) : "memory");
}
__device__ __forceinline__ u32 lds32(u32 a) {
    u32 v;
    asm volatile("ld.shared.b32 %0, [%1];" : "=r"(v) : "r"(a));
    return v;
}
// (a_hi at k-even = low half, a_lo at k-odd = high half)
__device__ __forceinline__ u32 asplit(float v) {
    __nv_bfloat16 h = __float2bfloat16_rn(v);
    float fh = __bfloat162float(h);
    __nv_bfloat16 lo = __float2bfloat16_rn(v - fh);
    return (u32)__bfloat16_as_ushort(h) | ((u32)__bfloat16_as_ushort(lo) << 16);
}
__device__ __forceinline__ void lda4(u32 addr, u32& a0, u32& a1, u32& a2, u32& a3) {
    asm volatile("ldmatrix.sync.aligned.m8n8.x4.shared.b16 {%0,%1,%2,%3}, [%4];"
                 : "=r"(a0), "=r"(a1), "=r"(a2), "=r"(a3) : "r"(addr));
}
__device__ __forceinline__ void mma16816(float* d, u32 a0, u32 a1, u32 a2, u32 a3, u32 b0, u32 b1) {
    asm volatile(
        "mma.sync.aligned.m16n8k16.row.col.f32.bf16.bf16.f32 "
        "{%0,%1,%2,%3}, {%4,%5,%6,%7}, {%8,%9}, {%0,%1,%2,%3};"
        : "+f"(d[0]), "+f"(d[1]), "+f"(d[2]), "+f"(d[3])
        : "r"(a0), "r"(a1), "r"(a2), "r"(a3), "r"(b0), "r"(b1));
}

__global__ __launch_bounds__(256, 1) void cnn_main(
    const float* __restrict__ x,
    const float* __restrict__ w1, const float* __restrict__ b1,
    const float* __restrict__ w2, const float* __restrict__ b2,
    const float* __restrict__ w3, const float* __restrict__ b3)
{
    extern __shared__ float smf[];
    const int tid = threadIdx.x;
    const int w_  = tid >> 5;
    const int l   = tid & 31;
    const int g   = l >> 2;
    const int t4  = l & 3;
    const bool act = ((g & 1) == 0);
    const int n   = blockIdx.x;
    const float* xin = x + (size_t)n * (TT * 9);

    float* sb   = smf;                 // 64 biases
    float* facc = smf + 64;            // [60][16]
    const u32 abase = smem_u32p(smf) + 4096u;

    // zero arena (pads/halos stay zero forever) + facc
    for (u32 o = 4u * tid; o < ABSZ; o += 1024u) sts32(abase + o, 0u);
    for (int i = tid; i < 960; i += 256) facc[i] = 0.f;
    if (tid < 16)      sb[tid] = b1[tid];
    else if (tid < 48) sb[tid] = b2[tid - 16];
    else if (tid < 64) sb[tid] = b3[tid - 48];

    // B: per-tap subtiles; per ci TWO pairs: (w_hi,w_hi) then (w_lo,0)
    for (int i = tid; i < 16 * 27; i += 256) {
        int co = i / 27, j = i - co * 27, ci = j / 3, kk = j - ci * 3;
        float v = w1[i];
        __nv_bfloat16 h = __float2bfloat16_rn(v);
        u32 hb = __bfloat16_as_ushort(h);
        u32 lb = __bfloat16_as_ushort(__float2bfloat16_rn(v - __bfloat162float(h)));
        sts64v(abase + OB1 + (u32)kk * B1TAP + (u32)(co * SA1 + ci * 8), hb | (hb << 16), lb);
    }
    for (int i = tid; i < 32 * 48; i += 256) {
        int co = i / 48, j = i - co * 48, ci = j / 3, kk = j - ci * 3;
        float v = w2[i];
        __nv_bfloat16 h = __float2bfloat16_rn(v);
        u32 hb = __bfloat16_as_ushort(h);
        u32 lb = __bfloat16_as_ushort(__float2bfloat16_rn(v - __bfloat162float(h)));
        sts64v(abase + OB2 + (u32)kk * B2TAP + (u32)(co * SA2 + ci * 8), hb | (hb << 16), lb);
    }
    for (int i = tid; i < 16 * 96; i += 256) {
        int co = i / 96, j = i - co * 96, ci = j / 3, kk = j - ci * 3;
        float v = w3[i];
        __nv_bfloat16 h = __float2bfloat16_rn(v);
        u32 hb = __bfloat16_as_ushort(h);
        u32 lb = __bfloat16_as_ushort(__float2bfloat16_rn(v - __bfloat162float(h)));
        sts64v(abase + OB3 + (u32)kk * B3TAP + (u32)(co * SA3 + ci * 8), hb | (hb << 16), lb);
    }
    __syncthreads();

    for (int tile = 0; tile < NT; ++tile) {
        const int va  = tile * V3T;
        const int u1b = 4 * va - 6;
        const int u2b = 2 * va - 2;
        const int tb  = 8 * va - 14;

        // ---- build A1 raw: row tl = split(x[tb+tl]) at both pairs (one STS.64) ----
        for (int idx = tid; idx < 514 * 9; idx += 256) {
            int tl = idx / 9, ci = idx - tl * 9;
            int t  = tb + tl;
            float v = ((unsigned)t < (unsigned)TT) ? xin[t * 9 + ci] : 0.f;
            u32 p = asplit(v);
            sts64v(abase + OA1 + (u32)(tl * SA1 + ci * 8), p, p);
        }
        __syncthreads();

        // ================= stage 1: 512 conv rows, N=16, K=2*9 pairs, 3 ksteps =================
        {
            float acc[4][2][4];
            #pragma unroll
            for (int mi = 0; mi < 4; ++mi)
                #pragma unroll
                for (int nf = 0; nf < 2; ++nf)
                    #pragma unroll
                    for (int q = 0; q < 4; ++q) acc[mi][nf][q] = 0.f;

            #pragma unroll
            for (int kk = 0; kk < 3; ++kk) {
                #pragma unroll
                for (int ks = 0; ks < 3; ++ks) {
                    u32 bA = abase + OB1 + (u32)kk * B1TAP + (u32)(g * SA1 + ks * 32 + t4 * 4);
                    u32 b00 = lds32(bA), b01 = lds32(bA + 16);
                    u32 b10 = lds32(bA + 8 * SA1), b11 = lds32(bA + 8 * SA1 + 16);
                    #pragma unroll
                    for (int mi = 0; mi < 4; ++mi) {
                        int row = 64 * w_ + 16 * mi + (l & 7) + 8 * ((l >> 3) & 1) + kk;
                        u32 a0, a1, a2, a3;
                        lda4(abase + OA1 + (u32)(row * SA1 + ks * 32 + ((l >> 4) & 1) * 16), a0, a1, a2, a3);
                        mma16816(acc[mi][0], a0, a1, a2, a3, b00, b01);
                        mma16816(acc[mi][1], a0, a1, a2, a3, b10, b11);
                    }
                }
            }
            // epilogue: pool(shfl^4) -> bias+relu -> one STS.64 into A2
            #pragma unroll
            for (int mi = 0; mi < 4; ++mi) {
                #pragma unroll
                for (int nf = 0; nf < 2; ++nf) {
                    float p0 = fmaxf(acc[mi][nf][0], __shfl_xor_sync(0xffffffffu, acc[mi][nf][0], 4));
                    float p1 = fmaxf(acc[mi][nf][1], __shfl_xor_sync(0xffffffffu, acc[mi][nf][1], 4));
                    float p2 = fmaxf(acc[mi][nf][2], __shfl_xor_sync(0xffffffffu, acc[mi][nf][2], 4));
                    float p3 = fmaxf(acc[mi][nf][3], __shfl_xor_sync(0xffffffffu, acc[mi][nf][3], 4));
                    if (act) {
                        int ua = 32 * w_ + 8 * mi + (g >> 1);
                        int j0 = nf * 8 + 2 * t4;
                        #pragma unroll
                        for (int s = 0; s < 4; ++s) {
                            int u = ua + ((s >> 1) ? 4 : 0);
                            int j = j0 + (s & 1);
                            float p = (s == 0) ? p0 : (s == 1) ? p1 : (s == 2) ? p2 : p3;
                            int gg = u + u1b;
                            float y = (u < 250 && gg >= 0 && gg < 2049) ? fmaxf(p + sb[j], 0.f) : 0.f;
                            u32 d = asplit(y);
                            sts64v(abase + OA2 + (u32)(u * SA2 + j * 8), d, d);
                        }
                    }
                }
            }
        }
        __syncthreads();

        // ================= stage 2: 256 conv rows, N=32, K=2*16 pairs, 4 ksteps =================
        {
            float acc[2][4][4];
            #pragma unroll
            for (int mi = 0; mi < 2; ++mi)
                #pragma unroll
                for (int nf = 0; nf < 4; ++nf)
                    #pragma unroll
                    for (int q = 0; q < 4; ++q) acc[mi][nf][q] = 0.f;

            #pragma unroll
            for (int kk = 0; kk < 3; ++kk) {
                #pragma unroll
                for (int ks = 0; ks < 4; ++ks) {
                    u32 bb[8];
                    #pragma unroll
                    for (int nf = 0; nf < 4; ++nf) {
                        u32 bA = abase + OB2 + (u32)kk * B2TAP
                               + (u32)((nf * 8 + g) * SA2 + ks * 32 + t4 * 4);
                        bb[2 * nf] = lds32(bA); bb[2 * nf + 1] = lds32(bA + 16);
                    }
                    #pragma unroll
                    for (int mi = 0; mi < 2; ++mi) {
                        int row = 32 * w_ + 16 * mi + (l & 7) + 8 * ((l >> 3) & 1) + kk;
                        u32 a0, a1, a2, a3;
                        lda4(abase + OA2 + (u32)(row * SA2 + ks * 32 + ((l >> 4) & 1) * 16), a0, a1, a2, a3);
                        #pragma unroll
                        for (int nf = 0; nf < 4; ++nf)
                            mma16816(acc[mi][nf], a0, a1, a2, a3, bb[2 * nf], bb[2 * nf + 1]);
                    }
                }
            }
            #pragma unroll
            for (int mi = 0; mi < 2; ++mi) {
                #pragma unroll
                for (int nf = 0; nf < 4; ++nf) {
                    float p0 = fmaxf(acc[mi][nf][0], __shfl_xor_sync(0xffffffffu, acc[mi][nf][0], 4));
                    float p1 = fmaxf(acc[mi][nf][1], __shfl_xor_sync(0xffffffffu, acc[mi][nf][1], 4));
                    float p2 = fmaxf(acc[mi][nf][2], __shfl_xor_sync(0xffffffffu, acc[mi][nf][2], 4));
                    float p3 = fmaxf(acc[mi][nf][3], __shfl_xor_sync(0xffffffffu, acc[mi][nf][3], 4));
                    if (act) {
                        int ua = 16 * w_ + 8 * mi + (g >> 1);
                        int j0 = nf * 8 + 2 * t4;
                        #pragma unroll
                        for (int s = 0; s < 4; ++s) {
                            int u = ua + ((s >> 1) ? 4 : 0);
                            int j = j0 + (s & 1);
                            float p = (s == 0) ? p0 : (s == 1) ? p1 : (s == 2) ? p2 : p3;
                            int gg = u + u2b;
                            float y = (u < 124 && gg >= 0 && gg < 1025) ? fmaxf(p + sb[16 + j], 0.f) : 0.f;
                            u32 d = asplit(y);
                            sts64v(abase + OA3 + (u32)(u * SA3 + j * 8), d, d);
                        }
                    }
                }
            }
        }
        __syncthreads();

        // ================= stage 3: 128 conv rows, N=16, K=2*32 pairs, 8 ksteps =================
        {
            float acc[2][4];
            #pragma unroll
            for (int nf = 0; nf < 2; ++nf)
                #pragma unroll
                for (int q = 0; q < 4; ++q) acc[nf][q] = 0.f;

            #pragma unroll
            for (int kk = 0; kk < 3; ++kk) {
                #pragma unroll
                for (int ks = 0; ks < 8; ++ks) {
                    u32 bA = abase + OB3 + (u32)kk * B3TAP + (u32)(g * SA3 + ks * 32 + t4 * 4);
                    u32 b00 = lds32(bA), b01 = lds32(bA + 16);
                    u32 b10 = lds32(bA + 8 * SA3), b11 = lds32(bA + 8 * SA3 + 16);
                    int row = 16 * w_ + (l & 7) + 8 * ((l >> 3) & 1) + kk;
                    u32 a0, a1, a2, a3;
                    lda4(abase + OA3 + (u32)(row * SA3 + ks * 32 + ((l >> 4) & 1) * 16), a0, a1, a2, a3);
                    mma16816(acc[0], a0, a1, a2, a3, b00, b01);
                    mma16816(acc[1], a0, a1, a2, a3, b10, b11);
                }
            }
            #pragma unroll
            for (int nf = 0; nf < 2; ++nf) {
                float p0 = fmaxf(acc[nf][0], __shfl_xor_sync(0xffffffffu, acc[nf][0], 4));
                float p1 = fmaxf(acc[nf][1], __shfl_xor_sync(0xffffffffu, acc[nf][1], 4));
                float p2 = fmaxf(acc[nf][2], __shfl_xor_sync(0xffffffffu, acc[nf][2], 4));
                float p3 = fmaxf(acc[nf][3], __shfl_xor_sync(0xffffffffu, acc[nf][3], 4));
                if (act) {
                    int va_ = 8 * w_ + (g >> 1);
                    int j0  = nf * 8 + 2 * t4;
                    #pragma unroll
                    for (int s = 0; s < 4; ++s) {
                        int v = va_ + ((s >> 1) ? 4 : 0);
                        int j = j0 + (s & 1);
                        float p = (s == 0) ? p0 : (s == 1) ? p1 : (s == 2) ? p2 : p3;
                        if (v < 60 && va + v < 513) {
                            float y = fmaxf(p + sb[48 + j], 0.f);
                            facc[v * 16 + j] += y;
                        }
                    }
                }
            }
        }
        __syncthreads();
    }

    // mean over 513 pooled positions
    if (tid < 16) {
        float s = 0.f;
        for (int v = 0; v < 60; ++v) s += facc[v * 16 + tid];
        g_feat[n * 16 + tid] = s * (1.0f / 513.0f);
    }
}

// Final: feat [B, J*16=128] -> maxpool k=3 -> [B, 42]
__global__ void final_pool(float* __restrict__ out)
{
    int i = blockIdx.x * blockDim.x + threadIdx.x;
    if (i >= 256 * 42) return;
    int b = i / 42, gg = i - b * 42;
    float m = -1e30f;
    #pragma unroll
    for (int e3 = 0; e3 < 3; ++e3) {
        int e = 3 * gg + e3;
        m = fmaxf(m, g_feat[(b * 8 + (e >> 4)) * 16 + (e & 15)]);
    }
    out[i] = m;
}

extern "C" void kernel_launch(void* const* d_in, const int* in_sizes, int n_in,
                              void* d_out, int out_size)
{
    (void)in_sizes; (void)n_in; (void)out_size;
    cudaFuncSetAttribute(cnn_main, cudaFuncAttributeMaxDynamicSharedMemorySize, SMEM_BYTES);
    cnn_main<<<NSEQ, 256, SMEM_BYTES>>>(
        (const float*)d_in[0],
        (const float*)d_in[1], (const float*)d_in[2],
        (const float*)d_in[3], (const float*)d_in[4],
        (const float*)d_in[5], (const float*)d_in[6]);
    final_pool<<<42, 256>>>((float*)d_out);
}

// round 9
// speedup vs baseline: 1.6205x; 1.6205x over previous
#include <cuda_runtime.h>

// Problem constants
#define TT    4096
#define FF    9
#define NSEQ  2048
#define L1    2049
#define L2    1025
#define L3    513

// Tiling
#define V3      62
#define NTILES  9
#define IN_LEN  (8*V3+14)       // 510
#define NLOAD   (IN_LEN*FF)     // 4590
#define IN_STR  516
#define S1_STR  264
#define S2_STR  132
#define W2_STR  49
#define W3_STR  97

#define SM_FLOATS (9*IN_STR + 16*S1_STR + 32*S2_STR + 432 + 32*W2_STR + 16*W3_STR + 64 + 256)
#define SMEM_BYTES (SM_FLOATS * 4)

__device__ float g_feat[NSEQ * 16];

__global__ void knop() {}

__global__ __launch_bounds__(256) void cnn_main(
    const float* __restrict__ x,
    const float* __restrict__ w1, const float* __restrict__ b1,
    const float* __restrict__ w2, const float* __restrict__ b2,
    const float* __restrict__ w3, const float* __restrict__ b3)
{
    extern __shared__ float sm[];
    float* h0  = sm;                      // [9][IN_STR]
    float* s1  = h0  + 9  * IN_STR;
    float* s2  = s1  + 16 * S1_STR;
    float* sw1 = s2  + 32 * S2_STR;
    float* sw2 = sw1 + 432;
    float* sw3 = sw2 + 32 * W2_STR;
    float* sb  = sw3 + 16 * W3_STR;
    float* facc= sb  + 64;

    const int tid = threadIdx.x;
    const int n   = blockIdx.x;
    const float* xin = x + (size_t)n * (TT * FF);

    // per-thread (tl, ci) start for the strided load/store walk (stride 256 = 28*9+4)
    const int tl0 = tid / 9;
    const int ci0 = tid - 9 * tl0;

    // Zero all smem once: persistent zero padding.
    for (int i = tid; i < SM_FLOATS; i += 256) sm[i] = 0.f;
    __syncthreads();

    for (int i = tid; i < 16*27; i += 256) sw1[i] = w1[i];
    for (int i = tid; i < 32*48; i += 256) sw2[(i/48)*W2_STR + (i%48)] = w2[i];
    for (int i = tid; i < 16*96; i += 256) sw3[(i/96)*W3_STR + (i%96)] = w3[i];
    if (tid < 16)      sb[tid] = b1[tid];
    else if (tid < 48) sb[tid] = b2[tid-16];
    else if (tid < 64) sb[tid] = b3[tid-48];
    __syncthreads();

    // ---- initial prefetch of tile 0 into registers ----
    float pf[18];
    {
        const int tb = -14;
        int tl = tl0, ci = ci0;
        #pragma unroll
        for (int it = 0; it < 18; ++it) {
            int idx = tid + (it << 8);
            int t   = tb + tl;
            float v = 0.f;
            if (idx < NLOAD && (unsigned)t < (unsigned)TT) v = xin[t*FF + ci];
            pf[it] = v;
            ci += 4; tl += 28; if (ci >= 9) { ci -= 9; ++tl; }
        }
    }

    for (int tile = 0; tile < NTILES; ++tile) {
        const int va  = tile * V3;
        const int vb  = min(va + V3, L3);
        const int u1b = 4*va - 6;
        const int u2b = 2*va - 2;

        // ---- Phase A: store prefetched regs -> h0 (pure STS) ----
        {
            int tl = tl0, ci = ci0;
            #pragma unroll
            for (int it = 0; it < 18; ++it) {
                int idx = tid + (it << 8);
                if (idx < NLOAD) h0[ci*IN_STR + tl] = pf[it];
                ci += 4; tl += 28; if (ci >= 9) { ci -= 9; ++tl; }
            }
        }
        __syncthreads();

        // ---- issue next tile's LDGs now; latency hidden by B/C/D ----
        if (tile + 1 < NTILES) {
            const int tb = 8*(va + V3) - 14;
            int tl = tl0, ci = ci0;
            #pragma unroll
            for (int it = 0; it < 18; ++it) {
                int idx = tid + (it << 8);
                int t   = tb + tl;
                float v = 0.f;
                if (idx < NLOAD && (unsigned)t < (unsigned)TT) v = xin[t*FF + ci];
                pf[it] = v;
                ci += 4; tl += 28; if (ci >= 9) { ci -= 9; ++tl; }
            }
        }

        // ---- Phase B: stage1 conv(9->16,k3,p2) + relu + pool2 ----
        #pragma unroll
        for (int it = 0; it < 2; ++it) {
            int item = tid + it*256;
            int cog = item & 7;
            int ug  = item >> 3;            // 0..63
            int co0 = cog * 2;
            int ul0 = ug * 4;
            float acc0[8], acc1[8];
            #pragma unroll
            for (int p = 0; p < 8; ++p) { acc0[p]=0.f; acc1[p]=0.f; }
            const float* wpa = sw1 + co0*27;
            const float* wpb = wpa + 27;
            const float* hp  = h0 + 2*ul0;
            #pragma unroll
            for (int ci = 0; ci < 9; ++ci) {
                float in[10];
                #pragma unroll
                for (int j = 0; j < 10; ++j) in[j] = hp[j];
                float wa0=wpa[0], wa1=wpa[1], wa2=wpa[2];
                float wb0=wpb[0], wb1=wpb[1], wb2=wpb[2];
                #pragma unroll
                for (int p = 0; p < 8; ++p) {
                    acc0[p] += wa0*in[p] + wa1*in[p+1] + wa2*in[p+2];
                    acc1[p] += wb0*in[p] + wb1*in[p+1] + wb2*in[p+2];
                }
                wpa += 3; wpb += 3; hp += IN_STR;
            }
            float ba = sb[co0], bb = sb[co0+1];
            #pragma unroll
            for (int u = 0; u < 4; ++u) {
                int ul  = ul0 + u;
                int ug1 = u1b + ul;
                bool valid = (ug1 >= 0) && (ug1 < L1);
                float v0 = fmaxf(fmaxf(acc0[2*u]+ba, 0.f), fmaxf(acc0[2*u+1]+ba, 0.f));
                float v1 = fmaxf(fmaxf(acc1[2*u]+bb, 0.f), fmaxf(acc1[2*u+1]+bb, 0.f));
                s1[ co0   *S1_STR + ul] = valid ? v0 : 0.f;
                s1[(co0+1)*S1_STR + ul] = valid ? v1 : 0.f;
            }
        }
        __syncthreads();

        // ---- Phase C: stage2 conv(16->32,k3,p2) + relu + pool2 ----
        #pragma unroll
        for (int it = 0; it < 2; ++it) {
            int item = tid + it*256;
            int cog = item & 15;
            int ug  = item >> 4;            // 0..31
            int co0 = cog * 2;
            int ul0 = ug * 4;
            float acc0[8], acc1[8];
            #pragma unroll
            for (int p = 0; p < 8; ++p) { acc0[p]=0.f; acc1[p]=0.f; }
            const float* wpa = sw2 + co0*W2_STR;
            const float* wpb = wpa + W2_STR;
            const float* hp  = s1 + 2*ul0;
            #pragma unroll 4
            for (int ci = 0; ci < 16; ++ci) {
                float in[10];
                #pragma unroll
                for (int j = 0; j < 10; ++j) in[j] = hp[j];
                float wa0=wpa[0], wa1=wpa[1], wa2=wpa[2];
                float wb0=wpb[0], wb1=wpb[1], wb2=wpb[2];
                #pragma unroll
                for (int p = 0; p < 8; ++p) {
                    acc0[p] += wa0*in[p] + wa1*in[p+1] + wa2*in[p+2];
                    acc1[p] += wb0*in[p] + wb1*in[p+1] + wb2*in[p+2];
                }
                wpa += 3; wpb += 3; hp += S1_STR;
            }
            float ba = sb[16+co0], bb = sb[16+co0+1];
            #pragma unroll
            for (int u = 0; u < 4; ++u) {
                int ul  = ul0 + u;
                int ug2 = u2b + ul;
                bool valid = (ug2 >= 0) && (ug2 < L2);
                float v0 = fmaxf(fmaxf(acc0[2*u]+ba, 0.f), fmaxf(acc0[2*u+1]+ba, 0.f));
                float v1 = fmaxf(fmaxf(acc1[2*u]+bb, 0.f), fmaxf(acc1[2*u+1]+bb, 0.f));
                s2[ co0   *S2_STR + ul] = valid ? v0 : 0.f;
                s2[(co0+1)*S2_STR + ul] = valid ? v1 : 0.f;
            }
        }
        __syncthreads();

        // ---- Phase D: stage3 conv(32->16,k3,p2) + relu + pool2 + mean-acc ----
        {
            int co  = tid & 15;
            int ug  = tid >> 4;
            int ul0 = ug * 4;
            float acc[8];
            #pragma unroll
            for (int p = 0; p < 8; ++p) acc[p] = 0.f;
            const float* wp = sw3 + co*W3_STR;
            const float* hp = s2 + 2*ul0;
            #pragma unroll 4
            for (int ci = 0; ci < 32; ++ci) {
                float in[10];
                #pragma unroll
                for (int j = 0; j < 10; ++j) in[j] = hp[j];
                float w0=wp[0], w1_=wp[1], w2_=wp[2];
                #pragma unroll
                for (int p = 0; p < 8; ++p)
                    acc[p] += w0*in[p] + w1_*in[p+1] + w2_*in[p+2];
                wp += 3; hp += S2_STR;
            }
            float b = sb[48+co];
            float sum = 0.f;
            #pragma unroll
            for (int u = 0; u < 4; ++u) {
                int v = va + ul0 + u;
                if (v < vb) {
                    float y = fmaxf(fmaxf(acc[2*u]+b, 0.f), fmaxf(acc[2*u+1]+b, 0.f));
                    sum += y;
                }
            }
            facc[tid] += sum;
        }
        __syncthreads();
    }

    // ---- mean over L3=513 positions ----
    if (tid < 16) {
        float s = 0.f;
        #pragma unroll
        for (int u = 0; u < 16; ++u) s += facc[tid + 16*u];
        g_feat[n*16 + tid] = s * (1.0f / 513.0f);
    }
}

// Final: feat [B, J*16=128] -> maxpool k=3 -> [B, 42]
__global__ void final_pool(float* __restrict__ out)
{
    int i = blockIdx.x * blockDim.x + threadIdx.x;
    if (i >= 256*42) return;
    int b = i / 42;
    int g = i - b*42;
    float m = -1e30f;
    #pragma unroll
    for (int e3 = 0; e3 < 3; ++e3) {
        int e = 3*g + e3;
        int j = e >> 4;
        int c = e & 15;
        m = fmaxf(m, g_feat[(b*8 + j)*16 + c]);
    }
    out[i] = m;
}

extern "C" void kernel_launch(void* const* d_in, const int* in_sizes, int n_in,
                              void* d_out, int out_size)
{
    (void)in_sizes; (void)n_in; (void)out_size;
    const float* x  = (const float*)d_in[0];
    const float* w1 = (const float*)d_in[1];
    const float* b1 = (const float*)d_in[2];
    const float* w2 = (const float*)d_in[3];
    const float* b2 = (const float*)d_in[4];
    const float* w3 = (const float*)d_in[5];
    const float* b3 = (const float*)d_in[6];
    float* out = (float*)d_out;

    cudaFuncSetAttribute(cnn_main, cudaFuncAttributeMaxDynamicSharedMemorySize, SMEM_BYTES);
    // 4 launches/call so ncu's "-s 5 -c 1" window (6th launch) lands on cnn_main
    knop<<<1, 32>>>();
    cnn_main<<<NSEQ, 256, SMEM_BYTES>>>(x, w1, b1, w2, b2, w3, b3);
    final_pool<<<42, 256>>>(out);
    knop<<<1, 32>>>();
}